// round 6
// baseline (speedup 1.0000x reference)
#include <cuda_runtime.h>
#include <cuda_fp16.h>
#include <cstdint>

namespace {

constexpr int NFREQ = 6;
constexpr int CIN   = 3 + 3 * 2 * NFREQ + 2 * 16;  // 71
constexpr int HID   = 32;
constexpr int TPB   = 128;
constexpr int NMAX  = 1048576;

// Merged geo+col channel-interleaved fp16 planes: (H, W, 32), ch0-15 geo, ch16-31 col.
__device__ __half g_tp[125829120];  // 252 MB
// Feature scratch: [chunk 0..7][point][8 halves] as uint4 per (chunk,point).
__device__ uint4 g_feat4[8 * NMAX];  // 128 MB

constexpr long long OFF_XY0 = 0LL;
constexpr long long OFF_XZ0 = 8388608LL;
constexpr long long OFF_YZ0 = 16777216LL;
constexpr long long OFF_XY1 = 25165824LL;
constexpr long long OFF_XZ1 = 58720256LL;
constexpr long long OFF_YZ1 = 92274688LL;

__constant__ int c_bnd[6]        = {0, 2048, 4096, 6144, 14336, 22528};
__constant__ long long c_dsto[6] = {OFF_XY0, OFF_XZ0, OFF_YZ0, OFF_XY1, OFF_XZ1, OFF_YZ1};
__constant__ int c_area[6]       = {262144, 262144, 262144, 1048576, 1048576, 1048576};

struct PackP {
  const float* geo[6];
  const float* col[6];
};

// Merged pack: all 6 plane-pairs in one launch. Block = 128 consecutive texels.
// Total blocks = 3*2048 + 3*8192 = 30720.
__global__ __launch_bounds__(128) void pack_all(PackP PP) {
  const int b = blockIdx.x;
  int pi = 0;
#pragma unroll
  for (int k = 1; k < 6; k++) pi += (b >= c_bnd[k]) ? 1 : 0;
  const int lb = b - c_bnd[pi];
  const int area = c_area[pi];
  const float* geo = PP.geo[pi];
  const float* col = PP.col[pi];

  __shared__ float sg[16 * 128];
  __shared__ float sc[16 * 128];
  const int base = lb * 128;
  const int t = threadIdx.x;
#pragma unroll
  for (int c = 0; c < 16; c++) {
    sg[c * 128 + t] = geo[(size_t)c * area + base + t];
    sc[c * 128 + t] = col[(size_t)c * area + base + t];
  }
  __syncthreads();
  uint4* out = reinterpret_cast<uint4*>(g_tp + c_dsto[pi] + (long long)base * 32);
#pragma unroll
  for (int i = t; i < 512; i += 128) {
    int texel = i >> 2, q = i & 3;
    const float* src = (q < 2) ? sg : sc;
    int ch0 = (q & 1) * 8;
    unsigned int u[4];
#pragma unroll
    for (int k = 0; k < 4; k++) {
      __half2 h = __floats2half2_rn(src[(ch0 + 2 * k) * 128 + texel],
                                    src[(ch0 + 2 * k + 1) * 128 + texel]);
      u[k] = *reinterpret_cast<unsigned int*>(&h);
    }
    out[i] = make_uint4(u[0], u[1], u[2], u[3]);
  }
}

__device__ __forceinline__ void acc8(uint4 v, float w, float* acc) {
  const __half2* h = reinterpret_cast<const __half2*>(&v);
#pragma unroll
  for (int k = 0; k < 4; k++) {
    float2 f = __half22float2(h[k]);
    acc[2 * k]     += w * f.x;
    acc[2 * k + 1] += w * f.y;
  }
}

// Bilinear sample of merged (H,W,32) fp16 plane; acc[0:16] geo, acc[16:32] col.
template <int R>
__device__ __forceinline__ void sample_pair(const __half* __restrict__ pl,
                                            float gx, float gy, float* acc) {
  const float rm1 = (float)(R - 1);
  float ix = fminf(fmaxf((gx + 1.0f) * 0.5f * rm1, 0.0f), rm1);
  float iy = fminf(fmaxf((gy + 1.0f) * 0.5f * rm1, 0.0f), rm1);
  float fx0 = floorf(ix), fy0 = floorf(iy);
  int x0 = (int)fx0, y0 = (int)fy0;
  int x1 = min(x0 + 1, R - 1);
  int y1 = min(y0 + 1, R - 1);
  float wx = ix - fx0, wy = iy - fy0;
  float w[4] = {(1.0f - wx) * (1.0f - wy), wx * (1.0f - wy),
                (1.0f - wx) * wy,          wx * wy};
  const uint4* cp[4] = {
    reinterpret_cast<const uint4*>(pl + ((size_t)(y0 * R + x0) << 5)),
    reinterpret_cast<const uint4*>(pl + ((size_t)(y0 * R + x1) << 5)),
    reinterpret_cast<const uint4*>(pl + ((size_t)(y1 * R + x0) << 5)),
    reinterpret_cast<const uint4*>(pl + ((size_t)(y1 * R + x1) << 5))};
#pragma unroll
  for (int k = 0; k < 4; k++) {
    uint4 v0 = __ldg(cp[k] + 0);
    uint4 v1 = __ldg(cp[k] + 1);
    uint4 v2 = __ldg(cp[k] + 2);
    uint4 v3 = __ldg(cp[k] + 3);
    acc8(v0, w[k], acc);
    acc8(v1, w[k], acc + 8);
    acc8(v2, w[k], acc + 16);
    acc8(v3, w[k], acc + 24);
  }
}

__device__ __forceinline__ uint4 pack_chunk(const float* a) {
  unsigned int u[4];
#pragma unroll
  for (int k = 0; k < 4; k++) {
    __half2 h = __floats2half2_rn(a[2 * k], a[2 * k + 1]);
    u[k] = *reinterpret_cast<unsigned int*>(&h);
  }
  return make_uint4(u[0], u[1], u[2], u[3]);
}

// Gather kernel: low live-set, level-by-level; writes fp16 feature chunks.
__global__ __launch_bounds__(TPB, 4) void gather_kernel(const float* __restrict__ p,
                                                        const float* __restrict__ bound,
                                                        int N) {
  const int idx = blockIdx.x * TPB + threadIdx.x;
  if (idx >= N) return;
  float px = p[3 * idx + 0];
  float py = p[3 * idx + 1];
  float pz = p[3 * idx + 2];
  float lo0 = __ldg(bound + 0), hi0 = __ldg(bound + 1);
  float lo1 = __ldg(bound + 2), hi1 = __ldg(bound + 3);
  float lo2 = __ldg(bound + 4), hi2 = __ldg(bound + 5);
  float nx = (px - lo0) / (hi0 - lo0);
  float ny = (py - lo1) / (hi1 - lo1);
  float nz = (pz - lo2) / (hi2 - lo2);

  float acc[32];
  // ---- level 0 ----
#pragma unroll
  for (int k = 0; k < 32; k++) acc[k] = 0.0f;
  sample_pair<512>(g_tp + OFF_XY0, nx, ny, acc);
  sample_pair<512>(g_tp + OFF_XZ0, nx, nz, acc);
  sample_pair<512>(g_tp + OFF_YZ0, ny, nz, acc);
#pragma unroll
  for (int c = 0; c < 4; c++) g_feat4[c * N + idx] = pack_chunk(acc + 8 * c);

  // ---- level 1 ----
#pragma unroll
  for (int k = 0; k < 32; k++) acc[k] = 0.0f;
  sample_pair<1024>(g_tp + OFF_XY1, nx, ny, acc);
  sample_pair<1024>(g_tp + OFF_XZ1, nx, nz, acc);
  sample_pair<1024>(g_tp + OFF_YZ1, ny, nz, acc);
#pragma unroll
  for (int c = 0; c < 4; c++) g_feat4[(4 + c) * N + idx] = pack_chunk(acc + 8 * c);
}

struct MlpP {
  const float* p;
  const float* bound;
  const float* W0;  const float* b0;
  const float* W1;  const float* b1;
  const float* Wo;  const float* bo;
  const float* cW0; const float* cb0;
  const float* cW1; const float* cb1;
  const float* cWo; const float* cbo;
  float* out;
  int N;
};

__device__ __forceinline__ void unpack_chunk(uint4 v, float* dst) {
  const __half2* h = reinterpret_cast<const __half2*>(&v);
#pragma unroll
  for (int k = 0; k < 4; k++) {
    float2 f = __half22float2(h[k]);
    dst[2 * k] = f.x;
    dst[2 * k + 1] = f.y;
  }
}

// dot of fp32 x[72] against an fp16 weight row (72 halves = 9 uint4)
__device__ __forceinline__ float dot72_h(const uint4* wr, const float* x, float s) {
#pragma unroll
  for (int i4 = 0; i4 < 9; i4++) {
    uint4 v = wr[i4];
    const __half2* h = reinterpret_cast<const __half2*>(&v);
#pragma unroll
    for (int k = 0; k < 4; k++) {
      float2 f = __half22float2(h[k]);
      s += x[8 * i4 + 2 * k] * f.x + x[8 * i4 + 2 * k + 1] * f.y;
    }
  }
  return s;
}

__device__ __forceinline__ float dot32_h(const uint4* wr, const float* x, float s) {
#pragma unroll
  for (int i4 = 0; i4 < 4; i4++) {
    uint4 v = wr[i4];
    const __half2* h = reinterpret_cast<const __half2*>(&v);
#pragma unroll
    for (int k = 0; k < 4; k++) {
      float2 f = __half22float2(h[k]);
      s += x[8 * i4 + 2 * k] * f.x + x[8 * i4 + 2 * k + 1] * f.y;
    }
  }
  return s;
}

__global__ __launch_bounds__(TPB, 3) void mlp_kernel(MlpP P) {
  // fp16 weights in smem (rows 16B-aligned): W0/cW0 rows of 72, W1/cW1 rows of 32.
  __shared__ __align__(16) __half sW0h[HID * 72];
  __shared__ __align__(16) __half scW0h[HID * 72];
  __shared__ __align__(16) __half sW1h[HID * 32];
  __shared__ __align__(16) __half scW1h[HID * 32];
  __shared__ float sb0[HID], sb1[HID], sWo[HID];
  __shared__ float scb0[HID], scb1[HID], scWo[3 * HID];
  __shared__ float sbo, scbo[3];

  const int t = threadIdx.x;
  for (int i = t; i < HID * 72; i += TPB) {
    int j = i / 72, c = i % 72;
    sW0h[i]  = __float2half((c < CIN) ? P.W0[j * CIN + c]  : 0.0f);
    scW0h[i] = __float2half((c < CIN) ? P.cW0[j * CIN + c] : 0.0f);
  }
  for (int i = t; i < HID * 32; i += TPB) {
    sW1h[i]  = __float2half(P.W1[i]);
    scW1h[i] = __float2half(P.cW1[i]);
  }
  if (t < HID) {
    sb0[t] = P.b0[t]; sb1[t] = P.b1[t]; sWo[t] = P.Wo[t];
    scb0[t] = P.cb0[t]; scb1[t] = P.cb1[t];
  }
  for (int i = t; i < 3 * HID; i += TPB) scWo[i] = P.cWo[i];
  if (t == 0) sbo = P.bo[0];
  if (t < 3) scbo[t] = P.cbo[t];
  __syncthreads();

  const int idx = blockIdx.x * TPB + t;
  if (idx >= P.N) return;

  float px = P.p[3 * idx + 0];
  float py = P.p[3 * idx + 1];
  float pz = P.p[3 * idx + 2];
  float lo0 = __ldg(P.bound + 0), hi0 = __ldg(P.bound + 1);
  float lo1 = __ldg(P.bound + 2), hi1 = __ldg(P.bound + 3);
  float lo2 = __ldg(P.bound + 4), hi2 = __ldg(P.bound + 5);
  float nx = (px - lo0) / (hi0 - lo0);
  float ny = (py - lo1) / (hi1 - lo1);
  float nz = (pz - lo2) / (hi2 - lo2);

  float x[72];
  x[0] = nx; x[1] = ny; x[2] = nz;
  float n3[3] = {nx, ny, nz};
#pragma unroll
  for (int f = 0; f < NFREQ; f++) {
    const float freq = 3.14159265358979323846f * (float)(1 << f);
#pragma unroll
    for (int a = 0; a < 3; a++) {
      float s, c;
      sincosf(n3[a] * freq, &s, &c);
      x[3 + f * 3 + a] = s;
      x[3 + 18 + f * 3 + a] = c;
    }
  }
  x[71] = 0.0f;

  // load feature chunks (coalesced LDG.128 per chunk)
  uint4 g0 = g_feat4[0 * P.N + idx], g1 = g_feat4[1 * P.N + idx];
  uint4 c0 = g_feat4[2 * P.N + idx], c1 = g_feat4[3 * P.N + idx];
  uint4 g2 = g_feat4[4 * P.N + idx], g3 = g_feat4[5 * P.N + idx];
  uint4 c2 = g_feat4[6 * P.N + idx], c3 = g_feat4[7 * P.N + idx];

  unpack_chunk(g0, x + 39);
  unpack_chunk(g1, x + 47);
  unpack_chunk(g2, x + 55);
  unpack_chunk(g3, x + 63);

  // ---- geometry MLP ----
  float h1[HID], h2[HID];
  for (int j = 0; j < HID; j++)
    h1[j] = fmaxf(dot72_h(reinterpret_cast<const uint4*>(sW0h + j * 72), x, sb0[j]), 0.0f);
  for (int j = 0; j < HID; j++)
    h2[j] = fmaxf(dot32_h(reinterpret_cast<const uint4*>(sW1h + j * 32), h1, sb1[j]), 0.0f);
  float sdf = sbo;
#pragma unroll
  for (int i = 0; i < HID; i++) sdf += h2[i] * sWo[i];
  sdf = tanhf(sdf);

  // ---- color MLP ----
  unpack_chunk(c0, x + 39);
  unpack_chunk(c1, x + 47);
  unpack_chunk(c2, x + 55);
  unpack_chunk(c3, x + 63);

  for (int j = 0; j < HID; j++)
    h1[j] = fmaxf(dot72_h(reinterpret_cast<const uint4*>(scW0h + j * 72), x, scb0[j]), 0.0f);
  for (int j = 0; j < HID; j++)
    h2[j] = fmaxf(dot32_h(reinterpret_cast<const uint4*>(scW1h + j * 32), h1, scb1[j]), 0.0f);
  float r = scbo[0], g = scbo[1], b = scbo[2];
#pragma unroll
  for (int i = 0; i < HID; i++) {
    r += h2[i] * scWo[0 * HID + i];
    g += h2[i] * scWo[1 * HID + i];
    b += h2[i] * scWo[2 * HID + i];
  }

  reinterpret_cast<float4*>(P.out)[idx] = make_float4(r, g, b, sdf);
}

}  // namespace

extern "C" void kernel_launch(void* const* d_in, const int* in_sizes, int n_in,
                              void* d_out, int out_size) {
  PackP PP;
  for (int i = 0; i < 6; i++) {
    PP.geo[i] = (const float*)d_in[2 + i];
    PP.col[i] = (const float*)d_in[8 + i];
  }
  pack_all<<<30720, 128>>>(PP);

  const float* p = (const float*)d_in[0];
  const float* bound = (const float*)d_in[1];
  int N = in_sizes[0] / 3;

  gather_kernel<<<(N + TPB - 1) / TPB, TPB>>>(p, bound, N);

  MlpP P;
  P.p = p; P.bound = bound;
  P.W0  = (const float*)d_in[14]; P.b0  = (const float*)d_in[15];
  P.W1  = (const float*)d_in[16]; P.b1  = (const float*)d_in[17];
  P.Wo  = (const float*)d_in[18]; P.bo  = (const float*)d_in[19];
  P.cW0 = (const float*)d_in[20]; P.cb0 = (const float*)d_in[21];
  P.cW1 = (const float*)d_in[22]; P.cb1 = (const float*)d_in[23];
  P.cWo = (const float*)d_in[24]; P.cbo = (const float*)d_in[25];
  P.out = (float*)d_out;
  P.N = N;

  mlp_kernel<<<(N + TPB - 1) / TPB, TPB>>>(P);
}

// round 7
// speedup vs baseline: 1.2863x; 1.2863x over previous
#include <cuda_runtime.h>
#include <cuda_fp16.h>
#include <cstdint>

namespace {

constexpr int NFREQ = 6;
constexpr int CIN   = 3 + 3 * 2 * NFREQ + 2 * 16;  // 71
constexpr int HID   = 32;
constexpr int TPB   = 128;
constexpr int NMAX  = 1048576;

// Merged geo+col channel-interleaved fp16 planes: (H, W, 32), texel = 64B:
// [geo ch0-7][geo ch8-15][col ch0-7][col ch8-15] as 4x uint4.
__device__ __half g_tp[125829120];  // 252 MB
// Feature scratch: [chunk 0..7][point] as uint4 (8 fp16 each).
// chunks 0,1 = L0 geo; 2,3 = L0 col; 4,5 = L1 geo; 6,7 = L1 col.
__device__ uint4 g_feat4[8 * NMAX];  // 128 MB

constexpr long long OFF_XY0 = 0LL;
constexpr long long OFF_XZ0 = 8388608LL;
constexpr long long OFF_YZ0 = 16777216LL;
constexpr long long OFF_XY1 = 25165824LL;
constexpr long long OFF_XZ1 = 58720256LL;
constexpr long long OFF_YZ1 = 92274688LL;

// ---------------- pack (reverted to per-pair launches; measured faster) ----------------
__global__ __launch_bounds__(128) void pack_pair(const float* __restrict__ geo,
                                                 const float* __restrict__ col,
                                                 long long dstoff, int area) {
  __shared__ float sg[16 * 128];
  __shared__ float sc[16 * 128];
  const int base = blockIdx.x * 128;
  const int t = threadIdx.x;
#pragma unroll
  for (int c = 0; c < 16; c++) {
    sg[c * 128 + t] = geo[(size_t)c * area + base + t];
    sc[c * 128 + t] = col[(size_t)c * area + base + t];
  }
  __syncthreads();
  uint4* out = reinterpret_cast<uint4*>(g_tp + dstoff + (long long)base * 32);
#pragma unroll
  for (int i = t; i < 512; i += 128) {
    int texel = i >> 2, q = i & 3;
    const float* src = (q < 2) ? sg : sc;
    int ch0 = (q & 1) * 8;
    unsigned int u[4];
#pragma unroll
    for (int k = 0; k < 4; k++) {
      __half2 h = __floats2half2_rn(src[(ch0 + 2 * k) * 128 + texel],
                                    src[(ch0 + 2 * k + 1) * 128 + texel]);
      u[k] = *reinterpret_cast<unsigned int*>(&h);
    }
    out[i] = make_uint4(u[0], u[1], u[2], u[3]);
  }
}

// ---------------- quad-cooperative gather ----------------
__device__ __forceinline__ void acc8q(uint4 v, float w, float* acc) {
  const __half2* h = reinterpret_cast<const __half2*>(&v);
#pragma unroll
  for (int k = 0; k < 4; k++) {
    float2 f = __half22float2(h[k]);
    acc[2 * k]     += w * f.x;
    acc[2 * k + 1] += w * f.y;
  }
}

// Lane r of a quad samples chunk r (16B) of all 4 corners of one plane.
template <int R>
__device__ __forceinline__ void sample_quad(const __half* __restrict__ pl,
                                            float gx, float gy, int r, float* acc) {
  const float rm1 = (float)(R - 1);
  float ix = fminf(fmaxf((gx + 1.0f) * 0.5f * rm1, 0.0f), rm1);
  float iy = fminf(fmaxf((gy + 1.0f) * 0.5f * rm1, 0.0f), rm1);
  float fx0 = floorf(ix), fy0 = floorf(iy);
  int x0 = (int)fx0, y0 = (int)fy0;
  int x1 = min(x0 + 1, R - 1);
  int y1 = min(y0 + 1, R - 1);
  float wx = ix - fx0, wy = iy - fy0;
  float w[4] = {(1.0f - wx) * (1.0f - wy), wx * (1.0f - wy),
                (1.0f - wx) * wy,          wx * wy};
  int o[4] = {y0 * R + x0, y0 * R + x1, y1 * R + x0, y1 * R + x1};
  uint4 v[4];
#pragma unroll
  for (int k = 0; k < 4; k++)
    v[k] = __ldg(reinterpret_cast<const uint4*>(pl + ((size_t)o[k] << 5)) + r);
#pragma unroll
  for (int k = 0; k < 4; k++) acc8q(v[k], w[k], acc);
}

__device__ __forceinline__ uint4 pack8(const float* a) {
  unsigned int u[4];
#pragma unroll
  for (int k = 0; k < 4; k++) {
    __half2 h = __floats2half2_rn(a[2 * k], a[2 * k + 1]);
    u[k] = *reinterpret_cast<unsigned int*>(&h);
  }
  return make_uint4(u[0], u[1], u[2], u[3]);
}

__global__ __launch_bounds__(256) void gather_kernel(const float* __restrict__ p,
                                                     const float* __restrict__ bound,
                                                     int N) {
  const int tid = blockIdx.x * 256 + threadIdx.x;
  const int idx = tid >> 2;
  const int r = tid & 3;
  if (idx >= N) return;

  float px = __ldg(p + 3 * idx + 0);
  float py = __ldg(p + 3 * idx + 1);
  float pz = __ldg(p + 3 * idx + 2);
  float lo0 = __ldg(bound + 0), hi0 = __ldg(bound + 1);
  float lo1 = __ldg(bound + 2), hi1 = __ldg(bound + 3);
  float lo2 = __ldg(bound + 4), hi2 = __ldg(bound + 5);
  float nx = (px - lo0) / (hi0 - lo0);
  float ny = (py - lo1) / (hi1 - lo1);
  float nz = (pz - lo2) / (hi2 - lo2);

  float acc[8];
  // ---- level 0 ----
#pragma unroll
  for (int k = 0; k < 8; k++) acc[k] = 0.0f;
  sample_quad<512>(g_tp + OFF_XY0, nx, ny, r, acc);
  sample_quad<512>(g_tp + OFF_XZ0, nx, nz, r, acc);
  sample_quad<512>(g_tp + OFF_YZ0, ny, nz, r, acc);
  g_feat4[r * N + idx] = pack8(acc);

  // ---- level 1 ----
#pragma unroll
  for (int k = 0; k < 8; k++) acc[k] = 0.0f;
  sample_quad<1024>(g_tp + OFF_XY1, nx, ny, r, acc);
  sample_quad<1024>(g_tp + OFF_XZ1, nx, nz, r, acc);
  sample_quad<1024>(g_tp + OFF_YZ1, ny, nz, r, acc);
  g_feat4[(4 + r) * N + idx] = pack8(acc);
}

// ---------------- MLP ----------------
struct MlpP {
  const float* p;
  const float* bound;
  const float* W0;  const float* b0;
  const float* W1;  const float* b1;
  const float* Wo;  const float* bo;
  const float* cW0; const float* cb0;
  const float* cW1; const float* cb1;
  const float* cWo; const float* cbo;
  float* out;
  int N;
};

__device__ __forceinline__ void unpack_chunk(uint4 v, float* dst) {
  const __half2* h = reinterpret_cast<const __half2*>(&v);
#pragma unroll
  for (int k = 0; k < 4; k++) {
    float2 f = __half22float2(h[k]);
    dst[2 * k] = f.x;
    dst[2 * k + 1] = f.y;
  }
}

__device__ __forceinline__ float dot72_h(const uint4* wr, const float* x, float s) {
#pragma unroll
  for (int i4 = 0; i4 < 9; i4++) {
    uint4 v = wr[i4];
    const __half2* h = reinterpret_cast<const __half2*>(&v);
#pragma unroll
    for (int k = 0; k < 4; k++) {
      float2 f = __half22float2(h[k]);
      s += x[8 * i4 + 2 * k] * f.x + x[8 * i4 + 2 * k + 1] * f.y;
    }
  }
  return s;
}

__device__ __forceinline__ float dot32_h(const uint4* wr, const float* x, float s) {
#pragma unroll
  for (int i4 = 0; i4 < 4; i4++) {
    uint4 v = wr[i4];
    const __half2* h = reinterpret_cast<const __half2*>(&v);
#pragma unroll
    for (int k = 0; k < 4; k++) {
      float2 f = __half22float2(h[k]);
      s += x[8 * i4 + 2 * k] * f.x + x[8 * i4 + 2 * k + 1] * f.y;
    }
  }
  return s;
}

__global__ __launch_bounds__(TPB, 3) void mlp_kernel(MlpP P) {
  __shared__ __align__(16) __half sW0h[HID * 72];
  __shared__ __align__(16) __half scW0h[HID * 72];
  __shared__ __align__(16) __half sW1h[HID * 32];
  __shared__ __align__(16) __half scW1h[HID * 32];
  __shared__ float sb0[HID], sb1[HID], sWo[HID];
  __shared__ float scb0[HID], scb1[HID], scWo[3 * HID];
  __shared__ float sbo, scbo[3];

  const int t = threadIdx.x;
  for (int i = t; i < HID * 72; i += TPB) {
    int j = i / 72, c = i % 72;
    sW0h[i]  = __float2half((c < CIN) ? P.W0[j * CIN + c]  : 0.0f);
    scW0h[i] = __float2half((c < CIN) ? P.cW0[j * CIN + c] : 0.0f);
  }
  for (int i = t; i < HID * 32; i += TPB) {
    sW1h[i]  = __float2half(P.W1[i]);
    scW1h[i] = __float2half(P.cW1[i]);
  }
  if (t < HID) {
    sb0[t] = P.b0[t]; sb1[t] = P.b1[t]; sWo[t] = P.Wo[t];
    scb0[t] = P.cb0[t]; scb1[t] = P.cb1[t];
  }
  for (int i = t; i < 3 * HID; i += TPB) scWo[i] = P.cWo[i];
  if (t == 0) sbo = P.bo[0];
  if (t < 3) scbo[t] = P.cbo[t];
  __syncthreads();

  const int idx = blockIdx.x * TPB + t;
  if (idx >= P.N) return;

  float px = P.p[3 * idx + 0];
  float py = P.p[3 * idx + 1];
  float pz = P.p[3 * idx + 2];
  float lo0 = __ldg(P.bound + 0), hi0 = __ldg(P.bound + 1);
  float lo1 = __ldg(P.bound + 2), hi1 = __ldg(P.bound + 3);
  float lo2 = __ldg(P.bound + 4), hi2 = __ldg(P.bound + 5);
  float nx = (px - lo0) / (hi0 - lo0);
  float ny = (py - lo1) / (hi1 - lo1);
  float nz = (pz - lo2) / (hi2 - lo2);

  float x[72];
  x[0] = nx; x[1] = ny; x[2] = nz;
  float n3[3] = {nx, ny, nz};
  // sincos via angle doubling: 3 sincosf + 5 doublings per axis.
#pragma unroll
  for (int a = 0; a < 3; a++) {
    float s, c;
    sincosf(n3[a] * 3.14159265358979323846f, &s, &c);
    x[3 + a]      = s;
    x[3 + 18 + a] = c;
#pragma unroll
    for (int f = 1; f < NFREQ; f++) {
      float s2 = 2.0f * s * c;
      float c2 = 1.0f - 2.0f * s * s;
      x[3 + f * 3 + a]      = s2;
      x[3 + 18 + f * 3 + a] = c2;
      s = s2; c = c2;
    }
  }
  x[71] = 0.0f;

  // coalesced fp16 feature chunks
  uint4 g0 = g_feat4[0 * P.N + idx], g1 = g_feat4[1 * P.N + idx];
  uint4 c0 = g_feat4[2 * P.N + idx], c1 = g_feat4[3 * P.N + idx];
  uint4 g2 = g_feat4[4 * P.N + idx], g3 = g_feat4[5 * P.N + idx];
  uint4 c2 = g_feat4[6 * P.N + idx], c3 = g_feat4[7 * P.N + idx];

  unpack_chunk(g0, x + 39);
  unpack_chunk(g1, x + 47);
  unpack_chunk(g2, x + 55);
  unpack_chunk(g3, x + 63);

  // ---- geometry MLP ----
  float h1[HID], h2[HID];
  for (int j = 0; j < HID; j++)
    h1[j] = fmaxf(dot72_h(reinterpret_cast<const uint4*>(sW0h + j * 72), x, sb0[j]), 0.0f);
  for (int j = 0; j < HID; j++)
    h2[j] = fmaxf(dot32_h(reinterpret_cast<const uint4*>(sW1h + j * 32), h1, sb1[j]), 0.0f);
  float sdf = sbo;
#pragma unroll
  for (int i = 0; i < HID; i++) sdf += h2[i] * sWo[i];
  sdf = tanhf(sdf);

  // ---- color MLP ----
  unpack_chunk(c0, x + 39);
  unpack_chunk(c1, x + 47);
  unpack_chunk(c2, x + 55);
  unpack_chunk(c3, x + 63);

  for (int j = 0; j < HID; j++)
    h1[j] = fmaxf(dot72_h(reinterpret_cast<const uint4*>(scW0h + j * 72), x, scb0[j]), 0.0f);
  for (int j = 0; j < HID; j++)
    h2[j] = fmaxf(dot32_h(reinterpret_cast<const uint4*>(scW1h + j * 32), h1, scb1[j]), 0.0f);
  float r = scbo[0], g = scbo[1], b = scbo[2];
#pragma unroll
  for (int i = 0; i < HID; i++) {
    r += h2[i] * scWo[0 * HID + i];
    g += h2[i] * scWo[1 * HID + i];
    b += h2[i] * scWo[2 * HID + i];
  }

  reinterpret_cast<float4*>(P.out)[idx] = make_float4(r, g, b, sdf);
}

}  // namespace

extern "C" void kernel_launch(void* const* d_in, const int* in_sizes, int n_in,
                              void* d_out, int out_size) {
  static const int areas[6] = {512 * 512, 512 * 512, 512 * 512,
                               1024 * 1024, 1024 * 1024, 1024 * 1024};
  static const long long offs[6] = {OFF_XY0, OFF_XZ0, OFF_YZ0,
                                    OFF_XY1, OFF_XZ1, OFF_YZ1};
  for (int i = 0; i < 6; i++) {
    pack_pair<<<areas[i] / 128, 128>>>((const float*)d_in[2 + i],
                                       (const float*)d_in[8 + i],
                                       offs[i], areas[i]);
  }

  const float* p = (const float*)d_in[0];
  const float* bound = (const float*)d_in[1];
  int N = in_sizes[0] / 3;

  gather_kernel<<<(4 * N + 255) / 256, 256>>>(p, bound, N);

  MlpP P;
  P.p = p; P.bound = bound;
  P.W0  = (const float*)d_in[14]; P.b0  = (const float*)d_in[15];
  P.W1  = (const float*)d_in[16]; P.b1  = (const float*)d_in[17];
  P.Wo  = (const float*)d_in[18]; P.bo  = (const float*)d_in[19];
  P.cW0 = (const float*)d_in[20]; P.cb0 = (const float*)d_in[21];
  P.cW1 = (const float*)d_in[22]; P.cb1 = (const float*)d_in[23];
  P.cWo = (const float*)d_in[24]; P.cbo = (const float*)d_in[25];
  P.out = (float*)d_out;
  P.N = N;

  mlp_kernel<<<(N + TPB - 1) / TPB, TPB>>>(P);
}

// round 8
// speedup vs baseline: 2.3241x; 1.8069x over previous
#include <cuda_runtime.h>
#include <cuda_fp16.h>
#include <cstdint>

namespace {

constexpr int NFREQ = 6;
constexpr int HID   = 32;
constexpr int NMAX  = 1048576;
constexpr int XS    = 88;   // X row stride in halves (conflict-free)
constexpr int WS1   = 40;   // W1 row stride in halves

// Merged geo+col channel-interleaved fp16 planes: (H, W, 32), texel = 64B:
// [geo ch0-7][geo ch8-15][col ch0-7][col ch8-15] as 4x uint4.
__device__ __half g_tp[125829120];  // 252 MB
// Feature scratch: [chunk 0..7][point] as uint4 (8 fp16 each).
// chunks 0,1 = L0 geo; 2,3 = L0 col; 4,5 = L1 geo; 6,7 = L1 col.
__device__ uint4 g_feat4[8 * NMAX];  // 128 MB

constexpr long long OFF_XY0 = 0LL;
constexpr long long OFF_XZ0 = 8388608LL;
constexpr long long OFF_YZ0 = 16777216LL;
constexpr long long OFF_XY1 = 25165824LL;
constexpr long long OFF_XZ1 = 58720256LL;
constexpr long long OFF_YZ1 = 92274688LL;

// ---------------- pack ----------------
__device__ __forceinline__ void pack_body(const float* __restrict__ geo,
                                          const float* __restrict__ col,
                                          long long dstoff, int area, int lb) {
  __shared__ float sg[16 * 128];
  __shared__ float sc[16 * 128];
  const int base = lb * 128;
  const int t = threadIdx.x;
#pragma unroll
  for (int c = 0; c < 16; c++) {
    sg[c * 128 + t] = geo[(size_t)c * area + base + t];
    sc[c * 128 + t] = col[(size_t)c * area + base + t];
  }
  __syncthreads();
  uint4* out = reinterpret_cast<uint4*>(g_tp + dstoff + (long long)base * 32);
#pragma unroll
  for (int i = t; i < 512; i += 128) {
    int texel = i >> 2, q = i & 3;
    const float* src = (q < 2) ? sg : sc;
    int ch0 = (q & 1) * 8;
    unsigned int u[4];
#pragma unroll
    for (int k = 0; k < 4; k++) {
      __half2 h = __floats2half2_rn(src[(ch0 + 2 * k) * 128 + texel],
                                    src[(ch0 + 2 * k + 1) * 128 + texel]);
      u[k] = *reinterpret_cast<unsigned int*>(&h);
    }
    out[i] = make_uint4(u[0], u[1], u[2], u[3]);
  }
}

struct Pack3 { const float* geo[3]; const float* col[3]; };

// All three 512-planes in one launch (uniform area; 2048 blocks each).
__global__ __launch_bounds__(128) void pack512_all(Pack3 PP) {
  int pi = blockIdx.x >> 11;
  int lb = blockIdx.x & 2047;
  long long dst = (pi == 0) ? OFF_XY0 : (pi == 1 ? OFF_XZ0 : OFF_YZ0);
  pack_body(PP.geo[pi], PP.col[pi], dst, 262144, lb);
}

__global__ __launch_bounds__(128) void pack_pair(const float* __restrict__ geo,
                                                 const float* __restrict__ col,
                                                 long long dstoff, int area) {
  pack_body(geo, col, dstoff, area, blockIdx.x);
}

// ---------------- quad-cooperative gather (unchanged from R7) ----------------
__device__ __forceinline__ void acc8q(uint4 v, float w, float* acc) {
  const __half2* h = reinterpret_cast<const __half2*>(&v);
#pragma unroll
  for (int k = 0; k < 4; k++) {
    float2 f = __half22float2(h[k]);
    acc[2 * k]     += w * f.x;
    acc[2 * k + 1] += w * f.y;
  }
}

template <int R>
__device__ __forceinline__ void sample_quad(const __half* __restrict__ pl,
                                            float gx, float gy, int r, float* acc) {
  const float rm1 = (float)(R - 1);
  float ix = fminf(fmaxf((gx + 1.0f) * 0.5f * rm1, 0.0f), rm1);
  float iy = fminf(fmaxf((gy + 1.0f) * 0.5f * rm1, 0.0f), rm1);
  float fx0 = floorf(ix), fy0 = floorf(iy);
  int x0 = (int)fx0, y0 = (int)fy0;
  int x1 = min(x0 + 1, R - 1);
  int y1 = min(y0 + 1, R - 1);
  float wx = ix - fx0, wy = iy - fy0;
  float w[4] = {(1.0f - wx) * (1.0f - wy), wx * (1.0f - wy),
                (1.0f - wx) * wy,          wx * wy};
  int o[4] = {y0 * R + x0, y0 * R + x1, y1 * R + x0, y1 * R + x1};
  uint4 v[4];
#pragma unroll
  for (int k = 0; k < 4; k++)
    v[k] = __ldg(reinterpret_cast<const uint4*>(pl + ((size_t)o[k] << 5)) + r);
#pragma unroll
  for (int k = 0; k < 4; k++) acc8q(v[k], w[k], acc);
}

__device__ __forceinline__ uint4 pack8(const float* a) {
  unsigned int u[4];
#pragma unroll
  for (int k = 0; k < 4; k++) {
    __half2 h = __floats2half2_rn(a[2 * k], a[2 * k + 1]);
    u[k] = *reinterpret_cast<unsigned int*>(&h);
  }
  return make_uint4(u[0], u[1], u[2], u[3]);
}

__global__ __launch_bounds__(256) void gather_kernel(const float* __restrict__ p,
                                                     const float* __restrict__ bound,
                                                     int N) {
  const int tid = blockIdx.x * 256 + threadIdx.x;
  const int idx = tid >> 2;
  const int r = tid & 3;
  if (idx >= N) return;

  float px = __ldg(p + 3 * idx + 0);
  float py = __ldg(p + 3 * idx + 1);
  float pz = __ldg(p + 3 * idx + 2);
  float lo0 = __ldg(bound + 0), hi0 = __ldg(bound + 1);
  float lo1 = __ldg(bound + 2), hi1 = __ldg(bound + 3);
  float lo2 = __ldg(bound + 4), hi2 = __ldg(bound + 5);
  float nx = (px - lo0) / (hi0 - lo0);
  float ny = (py - lo1) / (hi1 - lo1);
  float nz = (pz - lo2) / (hi2 - lo2);

  float acc[8];
#pragma unroll
  for (int k = 0; k < 8; k++) acc[k] = 0.0f;
  sample_quad<512>(g_tp + OFF_XY0, nx, ny, r, acc);
  sample_quad<512>(g_tp + OFF_XZ0, nx, nz, r, acc);
  sample_quad<512>(g_tp + OFF_YZ0, ny, nz, r, acc);
  g_feat4[r * N + idx] = pack8(acc);

#pragma unroll
  for (int k = 0; k < 8; k++) acc[k] = 0.0f;
  sample_quad<1024>(g_tp + OFF_XY1, nx, ny, r, acc);
  sample_quad<1024>(g_tp + OFF_XZ1, nx, nz, r, acc);
  sample_quad<1024>(g_tp + OFF_YZ1, ny, nz, r, acc);
  g_feat4[(4 + r) * N + idx] = pack8(acc);
}

// ---------------- tensor-core MLP ----------------
struct MlpP {
  const float* p;
  const float* bound;
  const float* W0;  const float* b0;
  const float* W1;  const float* b1;
  const float* Wo;  const float* bo;
  const float* cW0; const float* cb0;
  const float* cW1; const float* cb1;
  const float* cWo; const float* cbo;
  float* out;
  int N;
};

__device__ __forceinline__ void mma16816(float* d, const unsigned* a,
                                         unsigned b0, unsigned b1) {
  asm volatile(
      "mma.sync.aligned.m16n8k16.row.col.f32.f16.f16.f32 "
      "{%0,%1,%2,%3}, {%4,%5,%6,%7}, {%8,%9}, {%0,%1,%2,%3};"
      : "+f"(d[0]), "+f"(d[1]), "+f"(d[2]), "+f"(d[3])
      : "r"(a[0]), "r"(a[1]), "r"(a[2]), "r"(a[3]), "r"(b0), "r"(b1));
}

__device__ __forceinline__ unsigned packh2(float a, float b) {
  __half2 h = __floats2half2_rn(a, b);
  return *reinterpret_cast<unsigned*>(&h);
}

// X[128 x 80(fp16, stride XS)] @ W0^T -> relu -> @ W1^T ; acc2 = pre-bias h2 frags.
__device__ __forceinline__ void two_layer(const __half* X, const __half* W0s,
                                          const float* b0v, const __half* W1s,
                                          int rb, int g, int q,
                                          float acc2[2][4][4]) {
  float acc[2][4][4];
#pragma unroll
  for (int i = 0; i < 2; i++)
#pragma unroll
    for (int j = 0; j < 4; j++)
#pragma unroll
      for (int k = 0; k < 4; k++) acc[i][j][k] = 0.0f;

#pragma unroll
  for (int tk = 0; tk < 5; tk++) {
    unsigned a[2][4];
#pragma unroll
    for (int i = 0; i < 2; i++) {
      const __half* base = X + (rb + i * 16 + g) * XS + tk * 16 + q * 2;
      a[i][0] = *reinterpret_cast<const unsigned*>(base);
      a[i][1] = *reinterpret_cast<const unsigned*>(base + 8 * XS);
      a[i][2] = *reinterpret_cast<const unsigned*>(base + 8);
      a[i][3] = *reinterpret_cast<const unsigned*>(base + 8 * XS + 8);
    }
#pragma unroll
    for (int j = 0; j < 4; j++) {
      const __half* wb = W0s + (j * 8 + g) * XS + tk * 16 + q * 2;
      unsigned br0 = *reinterpret_cast<const unsigned*>(wb);
      unsigned br1 = *reinterpret_cast<const unsigned*>(wb + 8);
      mma16816(acc[0][j], a[0], br0, br1);
      mma16816(acc[1][j], a[1], br0, br1);
    }
  }

  float bj0[4], bj1[4];
#pragma unroll
  for (int j = 0; j < 4; j++) { bj0[j] = b0v[j * 8 + q * 2]; bj1[j] = b0v[j * 8 + q * 2 + 1]; }

#pragma unroll
  for (int i = 0; i < 2; i++)
#pragma unroll
    for (int j = 0; j < 4; j++)
#pragma unroll
      for (int k = 0; k < 4; k++) acc2[i][j][k] = 0.0f;

#pragma unroll
  for (int i = 0; i < 2; i++) {
    unsigned a2[2][4];
#pragma unroll
    for (int tk = 0; tk < 2; tk++) {
      int j0 = 2 * tk, j1 = j0 + 1;
      a2[tk][0] = packh2(fmaxf(acc[i][j0][0] + bj0[j0], 0.0f),
                         fmaxf(acc[i][j0][1] + bj1[j0], 0.0f));
      a2[tk][1] = packh2(fmaxf(acc[i][j0][2] + bj0[j0], 0.0f),
                         fmaxf(acc[i][j0][3] + bj1[j0], 0.0f));
      a2[tk][2] = packh2(fmaxf(acc[i][j1][0] + bj0[j1], 0.0f),
                         fmaxf(acc[i][j1][1] + bj1[j1], 0.0f));
      a2[tk][3] = packh2(fmaxf(acc[i][j1][2] + bj0[j1], 0.0f),
                         fmaxf(acc[i][j1][3] + bj1[j1], 0.0f));
    }
#pragma unroll
    for (int j = 0; j < 4; j++)
#pragma unroll
      for (int tk = 0; tk < 2; tk++) {
        const __half* wb = W1s + (j * 8 + g) * WS1 + tk * 16 + q * 2;
        mma16816(acc2[i][j], a2[tk],
                 *reinterpret_cast<const unsigned*>(wb),
                 *reinterpret_cast<const unsigned*>(wb + 8));
      }
  }
}

// Per-thread partial dot of relu(h2) against one output weight vector + quad reduce.
__device__ __forceinline__ void out_dots(const float acc2[2][4][4], const float* b1v,
                                         const float* wvec, int q, float res[2][2]) {
#pragma unroll
  for (int i = 0; i < 2; i++) { res[i][0] = 0.0f; res[i][1] = 0.0f; }
#pragma unroll
  for (int i = 0; i < 2; i++)
#pragma unroll
    for (int j = 0; j < 4; j++) {
      int c0 = j * 8 + q * 2, c1 = c0 + 1;
      float h00 = fmaxf(acc2[i][j][0] + b1v[c0], 0.0f);
      float h01 = fmaxf(acc2[i][j][1] + b1v[c1], 0.0f);
      float h10 = fmaxf(acc2[i][j][2] + b1v[c0], 0.0f);
      float h11 = fmaxf(acc2[i][j][3] + b1v[c1], 0.0f);
      res[i][0] += wvec[c0] * h00 + wvec[c1] * h01;
      res[i][1] += wvec[c0] * h10 + wvec[c1] * h11;
    }
#pragma unroll
  for (int i = 0; i < 2; i++)
#pragma unroll
    for (int k = 0; k < 2; k++) {
      res[i][k] += __shfl_xor_sync(0xffffffffu, res[i][k], 1);
      res[i][k] += __shfl_xor_sync(0xffffffffu, res[i][k], 2);
    }
}

__global__ __launch_bounds__(128) void mlp_kernel(MlpP P) {
  extern __shared__ __align__(16) char dsm[];
  __half* Xg   = reinterpret_cast<__half*>(dsm);             // 128*XS
  __half* Xc   = Xg + 128 * XS;                              // 128*XS
  __half* W0s  = Xc + 128 * XS;                              // 32*XS
  __half* cW0s = W0s + 32 * XS;
  __half* W1s  = cW0s + 32 * XS;                             // 32*WS1
  __half* cW1s = W1s + 32 * WS1;
  float* fb    = reinterpret_cast<float*>(cW1s + 32 * WS1);
  float* sb0 = fb;        float* sb1 = fb + 32;  float* sWo = fb + 64;
  float* scb0 = fb + 96;  float* scb1 = fb + 128; float* scWo = fb + 160;  // 96
  float* sext = fb + 256;  // [0]=bo, [1..3]=cbo

  const int t = threadIdx.x;
  // weights: input cols 0..38 = emb, 39 = pad, 40..71 = features, 72..87 = pad
  for (int i = t; i < 32 * XS; i += 128) {
    int j = i / XS, c = i % XS;
    float w0v = 0.0f, cw0v = 0.0f;
    if (c < 39)               { w0v = P.W0[j * 71 + c];     cw0v = P.cW0[j * 71 + c]; }
    else if (c >= 40 && c < 72) { w0v = P.W0[j * 71 + c - 1]; cw0v = P.cW0[j * 71 + c - 1]; }
    W0s[i] = __float2half(w0v);
    cW0s[i] = __float2half(cw0v);
  }
  for (int i = t; i < 32 * WS1; i += 128) {
    int j = i / WS1, c = i % WS1;
    W1s[i]  = __float2half(c < 32 ? P.W1[j * 32 + c]  : 0.0f);
    cW1s[i] = __float2half(c < 32 ? P.cW1[j * 32 + c] : 0.0f);
  }
  if (t < 32) {
    sb0[t] = P.b0[t]; sb1[t] = P.b1[t]; sWo[t] = P.Wo[t];
    scb0[t] = P.cb0[t]; scb1[t] = P.cb1[t];
  }
  for (int i = t; i < 96; i += 128) scWo[i] = P.cWo[i];
  if (t == 0) sext[0] = P.bo[0];
  if (t < 3) sext[1 + t] = P.cbo[t];

  // ---- phase 1: build input rows ----
  const int idx = blockIdx.x * 128 + t;
  uint4* rg = reinterpret_cast<uint4*>(Xg + t * XS);
  uint4* rc = reinterpret_cast<uint4*>(Xc + t * XS);
  if (idx < P.N) {
    float px = P.p[3 * idx + 0];
    float py = P.p[3 * idx + 1];
    float pz = P.p[3 * idx + 2];
    float lo0 = __ldg(P.bound + 0), hi0 = __ldg(P.bound + 1);
    float lo1 = __ldg(P.bound + 2), hi1 = __ldg(P.bound + 3);
    float lo2 = __ldg(P.bound + 4), hi2 = __ldg(P.bound + 5);
    float x[40];
    x[0] = (px - lo0) / (hi0 - lo0);
    x[1] = (py - lo1) / (hi1 - lo1);
    x[2] = (pz - lo2) / (hi2 - lo2);
#pragma unroll
    for (int a = 0; a < 3; a++) {
      float s, c;
      sincosf(x[a] * 3.14159265358979323846f, &s, &c);
      x[3 + a] = s;
      x[21 + a] = c;
#pragma unroll
      for (int f = 1; f < NFREQ; f++) {
        float s2 = 2.0f * s * c;
        float c2 = 1.0f - 2.0f * s * s;
        x[3 + f * 3 + a] = s2;
        x[21 + f * 3 + a] = c2;
        s = s2; c = c2;
      }
    }
    x[39] = 0.0f;
#pragma unroll
    for (int w = 0; w < 5; w++) {
      uint4 v = make_uint4(packh2(x[8 * w], x[8 * w + 1]), packh2(x[8 * w + 2], x[8 * w + 3]),
                           packh2(x[8 * w + 4], x[8 * w + 5]), packh2(x[8 * w + 6], x[8 * w + 7]));
      rg[w] = v; rc[w] = v;
    }
    // features straight from gather scratch (already fp16)
    rg[5] = g_feat4[0 * P.N + idx];
    rg[6] = g_feat4[1 * P.N + idx];
    rg[7] = g_feat4[4 * P.N + idx];
    rg[8] = g_feat4[5 * P.N + idx];
    rc[5] = g_feat4[2 * P.N + idx];
    rc[6] = g_feat4[3 * P.N + idx];
    rc[7] = g_feat4[6 * P.N + idx];
    rc[8] = g_feat4[7 * P.N + idx];
  } else {
    uint4 z = make_uint4(0, 0, 0, 0);
#pragma unroll
    for (int w = 0; w < 9; w++) { rg[w] = z; rc[w] = z; }
  }
  {
    uint4 z = make_uint4(0, 0, 0, 0);
    rg[9] = z; rg[10] = z; rc[9] = z; rc[10] = z;
  }
  __syncthreads();

  // ---- phase 2: tensor-core GEMMs ----
  const int wid = t >> 5, lane = t & 31, g = lane >> 2, q = lane & 3;
  const int rb = wid * 32;

  float sdfv[2][2], rv[2][2], gv[2][2], bv[2][2];
  {
    float acc2[2][4][4];
    two_layer(Xg, W0s, sb0, W1s, rb, g, q, acc2);
    out_dots(acc2, sb1, sWo, q, sdfv);
#pragma unroll
    for (int i = 0; i < 2; i++)
#pragma unroll
      for (int k = 0; k < 2; k++) sdfv[i][k] = tanhf(sdfv[i][k] + sext[0]);
  }
  {
    float acc2[2][4][4];
    two_layer(Xc, cW0s, scb0, cW1s, rb, g, q, acc2);
    out_dots(acc2, scb1, scWo + 0,  q, rv);
    out_dots(acc2, scb1, scWo + 32, q, gv);
    out_dots(acc2, scb1, scWo + 64, q, bv);
  }

  if (q == 0) {
    float4* out4 = reinterpret_cast<float4*>(P.out);
#pragma unroll
    for (int i = 0; i < 2; i++) {
      int r0 = blockIdx.x * 128 + rb + i * 16 + g;
      if (r0 < P.N)
        out4[r0] = make_float4(rv[i][0] + sext[1], gv[i][0] + sext[2],
                               bv[i][0] + sext[3], sdfv[i][0]);
      if (r0 + 8 < P.N)
        out4[r0 + 8] = make_float4(rv[i][1] + sext[1], gv[i][1] + sext[2],
                                   bv[i][1] + sext[3], sdfv[i][1]);
    }
  }
}

constexpr int MLP_SMEM = (2 * 128 * XS + 2 * 32 * XS + 2 * 32 * WS1) * 2 + 260 * 4;

}  // namespace

extern "C" void kernel_launch(void* const* d_in, const int* in_sizes, int n_in,
                              void* d_out, int out_size) {
  // pack: 1 launch for the three 512-pairs, 3 launches for 1024-pairs
  Pack3 P3;
  for (int i = 0; i < 3; i++) {
    P3.geo[i] = (const float*)d_in[2 + i];
    P3.col[i] = (const float*)d_in[8 + i];
  }
  pack512_all<<<6144, 128>>>(P3);
  static const long long offs1[3] = {OFF_XY1, OFF_XZ1, OFF_YZ1};
  for (int i = 0; i < 3; i++) {
    pack_pair<<<8192, 128>>>((const float*)d_in[5 + i], (const float*)d_in[11 + i],
                             offs1[i], 1048576);
  }

  const float* p = (const float*)d_in[0];
  const float* bound = (const float*)d_in[1];
  int N = in_sizes[0] / 3;

  gather_kernel<<<(4 * N + 255) / 256, 256>>>(p, bound, N);

  MlpP P;
  P.p = p; P.bound = bound;
  P.W0  = (const float*)d_in[14]; P.b0  = (const float*)d_in[15];
  P.W1  = (const float*)d_in[16]; P.b1  = (const float*)d_in[17];
  P.Wo  = (const float*)d_in[18]; P.bo  = (const float*)d_in[19];
  P.cW0 = (const float*)d_in[20]; P.cb0 = (const float*)d_in[21];
  P.cW1 = (const float*)d_in[22]; P.cb1 = (const float*)d_in[23];
  P.cWo = (const float*)d_in[24]; P.cbo = (const float*)d_in[25];
  P.out = (float*)d_out;
  P.N = N;

  cudaFuncSetAttribute(mlp_kernel, cudaFuncAttributeMaxDynamicSharedMemorySize, MLP_SMEM);
  mlp_kernel<<<(N + 127) / 128, 128, MLP_SMEM>>>(P);
}